// round 1
// baseline (speedup 1.0000x reference)
#include <cuda_runtime.h>
#include <math.h>

#define H 2048
#define L 350
#define H4 (H/4)          // 512 float4 per H-length vector

// -------- scratch (no allocations allowed) --------
__device__ float g_logits[L];
__device__ float g_gh[3*H];       // w_hh @ h + b_hh
__device__ float g_ctx[H];        // context vector
__device__ float g_g[H];          // relu(comb) vector

__device__ __forceinline__ float warp_sum(float v) {
    #pragma unroll
    for (int o = 16; o > 0; o >>= 1) v += __shfl_xor_sync(0xffffffffu, v, o);
    return v;
}

// ============================================================
// Kernel 1: attn logits (350 rows x 4096) + gh (6144 rows x 2048)
// warp-per-row
// ============================================================
__global__ __launch_bounds__(256) void k_phase1(
    const float* __restrict__ x, const float* __restrict__ h,
    const float* __restrict__ attn_W, const float* __restrict__ attn_b,
    const float* __restrict__ w_hh, const float* __restrict__ b_hh)
{
    int warp = (blockIdx.x * blockDim.x + threadIdx.x) >> 5;
    int lane = threadIdx.x & 31;
    const float4* x4 = (const float4*)x;
    const float4* h4 = (const float4*)h;

    if (warp < L) {
        // attn logit row: dot(attn_W[warp, 0:2048], x) + dot(attn_W[warp, 2048:4096], h)
        const float4* W = (const float4*)(attn_W + (size_t)warp * 2 * H);
        float s = 0.f;
        #pragma unroll 4
        for (int i = lane; i < H4; i += 32) {
            float4 w = W[i], v = x4[i];
            s += w.x*v.x + w.y*v.y + w.z*v.z + w.w*v.w;
        }
        #pragma unroll 4
        for (int i = lane; i < H4; i += 32) {
            float4 w = W[H4 + i], v = h4[i];
            s += w.x*v.x + w.y*v.y + w.z*v.z + w.w*v.w;
        }
        s = warp_sum(s);
        if (lane == 0) g_logits[warp] = s + attn_b[warp];
    } else if (warp < L + 3*H) {
        int r = warp - L;
        const float4* W = (const float4*)(w_hh + (size_t)r * H);
        float s = 0.f;
        #pragma unroll 4
        for (int i = lane; i < H4; i += 32) {
            float4 w = W[i], v = h4[i];
            s += w.x*v.x + w.y*v.y + w.z*v.z + w.w*v.w;
        }
        s = warp_sum(s);
        if (lane == 0) g_gh[r] = s + b_hh[r];
    }
}

// ============================================================
// Kernel 2: softmax(logits) fused with context = w @ encoder_outputs
// grid: 16 blocks x 128 threads; each block owns 128 context columns.
// block 0 additionally writes attn_weights to d_out[4096..4445].
// ============================================================
__global__ __launch_bounds__(128) void k_softmax_ctx(
    const float* __restrict__ enc, float* __restrict__ out)
{
    __shared__ float sw[L];
    __shared__ float red[128];
    int tid = threadIdx.x;

    // local max
    float m = -INFINITY;
    for (int i = tid; i < L; i += 128) { float v = g_logits[i]; sw[i] = v; m = fmaxf(m, v); }
    red[tid] = m; __syncthreads();
    #pragma unroll
    for (int s = 64; s > 0; s >>= 1) { if (tid < s) red[tid] = fmaxf(red[tid], red[tid + s]); __syncthreads(); }
    float mx = red[0]; __syncthreads();

    float sum = 0.f;
    for (int i = tid; i < L; i += 128) { float e = __expf(sw[i] - mx); sw[i] = e; sum += e; }
    red[tid] = sum; __syncthreads();
    #pragma unroll
    for (int s = 64; s > 0; s >>= 1) { if (tid < s) red[tid] += red[tid + s]; __syncthreads(); }
    float inv = 1.f / red[0]; __syncthreads();
    for (int i = tid; i < L; i += 128) sw[i] *= inv;
    __syncthreads();

    // context column j
    int j = blockIdx.x * 128 + tid;   // 16*128 = 2048 = H
    float acc = 0.f;
    #pragma unroll 2
    for (int i = 0; i < L; ++i) acc += sw[i] * enc[(size_t)i * H + j];
    g_ctx[j] = acc;

    if (blockIdx.x == 0)
        for (int i = tid; i < L; i += 128) out[2*H + i] = sw[i];
}

// ============================================================
// Kernel 3: g = relu(comb_W @ [x; ctx] + comb_b)   (2048 rows x 4096)
// warp-per-row
// ============================================================
__global__ __launch_bounds__(256) void k_comb(
    const float* __restrict__ x,
    const float* __restrict__ comb_W, const float* __restrict__ comb_b)
{
    int warp = (blockIdx.x * blockDim.x + threadIdx.x) >> 5;
    int lane = threadIdx.x & 31;
    if (warp >= H) return;
    const float4* x4 = (const float4*)x;
    const float4* c4 = (const float4*)g_ctx;
    const float4* W  = (const float4*)(comb_W + (size_t)warp * 2 * H);
    float s = 0.f;
    #pragma unroll 4
    for (int i = lane; i < H4; i += 32) {
        float4 w = W[i], v = x4[i];
        s += w.x*v.x + w.y*v.y + w.z*v.z + w.w*v.w;
    }
    #pragma unroll 4
    for (int i = lane; i < H4; i += 32) {
        float4 w = W[H4 + i], v = c4[i];
        s += w.x*v.x + w.y*v.y + w.z*v.z + w.w*v.w;
    }
    s = warp_sum(s);
    if (lane == 0) g_g[warp] = fmaxf(s + comb_b[warp], 0.f);
}

// ============================================================
// Kernel 4: gi = w_ih @ g (all 3 gate rows per warp) + GRU gate math + output
// warp j handles output element j.
// ============================================================
__global__ __launch_bounds__(256) void k_gru(
    const float* __restrict__ h,
    const float* __restrict__ w_ih, const float* __restrict__ b_ih,
    float* __restrict__ out)
{
    int warp = (blockIdx.x * blockDim.x + threadIdx.x) >> 5;
    int lane = threadIdx.x & 31;
    if (warp >= H) return;
    const float4* g4 = (const float4*)g_g;
    const float4* Wr = (const float4*)(w_ih + (size_t)warp * H);
    const float4* Wz = (const float4*)(w_ih + (size_t)(warp + H) * H);
    const float4* Wn = (const float4*)(w_ih + (size_t)(warp + 2*H) * H);
    float sr = 0.f, sz = 0.f, sn = 0.f;
    #pragma unroll 4
    for (int i = lane; i < H4; i += 32) {
        float4 v = g4[i];
        float4 a = Wr[i], b = Wz[i], c = Wn[i];
        sr += a.x*v.x + a.y*v.y + a.z*v.z + a.w*v.w;
        sz += b.x*v.x + b.y*v.y + b.z*v.z + b.w*v.w;
        sn += c.x*v.x + c.y*v.y + c.z*v.z + c.w*v.w;
    }
    sr = warp_sum(sr); sz = warp_sum(sz); sn = warp_sum(sn);
    if (lane == 0) {
        float ir = sr + b_ih[warp]         + g_gh[warp];
        float iz = sz + b_ih[warp + H]     + g_gh[warp + H];
        float r  = 1.f / (1.f + __expf(-ir));
        float z  = 1.f / (1.f + __expf(-iz));
        float n  = tanhf(sn + b_ih[warp + 2*H] + r * g_gh[warp + 2*H]);
        float hn = (1.f - z) * n + z * h[warp];
        out[warp]     = hn;   // output (1,1,H)
        out[H + warp] = hn;   // hidden (1,1,H)
    }
}

// ============================================================
extern "C" void kernel_launch(void* const* d_in, const int* in_sizes, int n_in,
                              void* d_out, int out_size)
{
    const float* x      = (const float*)d_in[0];   // input  (1,1,H)
    const float* h      = (const float*)d_in[1];   // hidden (1,1,H)
    const float* enc    = (const float*)d_in[2];   // (L,H)
    const float* attn_W = (const float*)d_in[3];   // (L,2H)
    const float* attn_b = (const float*)d_in[4];   // (L)
    const float* comb_W = (const float*)d_in[5];   // (H,2H)
    const float* comb_b = (const float*)d_in[6];   // (H)
    const float* w_ih   = (const float*)d_in[7];   // (3H,H)
    const float* w_hh   = (const float*)d_in[8];   // (3H,H)
    const float* b_ih   = (const float*)d_in[9];   // (3H)
    const float* b_hh   = (const float*)d_in[10];  // (3H)
    float* out = (float*)d_out;

    // phase1: L + 3H = 6494 warp-rows, 8 warps/block
    int rows1 = L + 3*H;
    int blocks1 = (rows1 + 7) / 8;
    k_phase1<<<blocks1, 256>>>(x, h, attn_W, attn_b, w_hh, b_hh);

    k_softmax_ctx<<<H / 128, 128>>>(enc, out);

    k_comb<<<H / 8, 256>>>(x, comb_W, comb_b);

    k_gru<<<H / 8, 256>>>(h, w_ih, b_ih, out);
}

// round 3
// speedup vs baseline: 2.8809x; 2.8809x over previous
#include <cuda_runtime.h>
#include <math.h>

#define H 2048
#define L 350
#define H4 (H/4)            // 512 float4 per H vector

// -------- persistent scratch (no allocs allowed) --------
__device__ float g_logits[L];
__device__ float g_w[L];            // softmax weights
__device__ float g_gh[3*H];         // w_hh @ h + b_hh
// atomically-accumulated scratch, zeroed each replay by k_phase1:
#define SC_CTX   0                  // [2048] context
#define SC_GSUM  2048               // [2048] comb matvec sum (pre-bias/relu)
#define SC_GI    4096               // [6144] w_ih @ g
#define SC_TOTAL (4096 + 3*H)       // 10240 floats
__device__ float g_scr[SC_TOTAL];

__device__ __forceinline__ float warp_sum(float v) {
    #pragma unroll
    for (int o = 16; o > 0; o >>= 1) v += __shfl_xor_sync(0xffffffffu, v, o);
    return v;
}
__device__ __forceinline__ float dot4(float4 a, float4 b) {
    return a.x*b.x + a.y*b.y + a.z*b.z + a.w*b.w;
}

// ============================================================
// Kernel 1: attn logits (350 warps, dual-stream) +
//           gh = w_hh@h + b_hh (3072 warps, 2 rows each) +
//           zero g_scr (80 warps)
// ============================================================
#define ZERO_WARPS ((SC_TOTAL + 127) / 128)      // 80
#define P1_WARPS   (L + 3*H/2 + ZERO_WARPS)      // 350 + 3072 + 80 = 3502
__global__ __launch_bounds__(256) void k_phase1(
    const float* __restrict__ x, const float* __restrict__ h,
    const float* __restrict__ attn_W, const float* __restrict__ attn_b,
    const float* __restrict__ w_hh, const float* __restrict__ b_hh)
{
    int warp = (blockIdx.x * blockDim.x + threadIdx.x) >> 5;
    int lane = threadIdx.x & 31;
    const float4* x4 = (const float4*)x;
    const float4* h4 = (const float4*)h;

    if (warp < L) {
        // interleaved x-part / h-part streams for MLP
        const float4* W = (const float4*)(attn_W + (size_t)warp * 2 * H);
        float s = 0.f;
        #pragma unroll 4
        for (int i = lane; i < H4; i += 32) {
            s += dot4(W[i], x4[i]);
            s += dot4(W[H4 + i], h4[i]);
        }
        s = warp_sum(s);
        if (lane == 0) g_logits[warp] = s + attn_b[warp];
    } else if (warp < L + 3*H/2) {
        int r = warp - L;              // 0..3071 -> rows r and r+3072
        const float4* W1 = (const float4*)(w_hh + (size_t)r * H);
        const float4* W2 = (const float4*)(w_hh + (size_t)(r + 3*H/2) * H);
        float s1 = 0.f, s2 = 0.f;
        #pragma unroll 4
        for (int i = lane; i < H4; i += 32) {
            float4 v = h4[i];
            s1 += dot4(W1[i], v);
            s2 += dot4(W2[i], v);
        }
        s1 = warp_sum(s1); s2 = warp_sum(s2);
        if (lane == 0) {
            g_gh[r]         = s1 + b_hh[r];
            g_gh[r + 3*H/2] = s2 + b_hh[r + 3*H/2];
        }
    } else if (warp < P1_WARPS) {
        int z = warp - (L + 3*H/2);
        int base = z * 128 + lane * 4;
        if (base < SC_TOTAL)
            *(float4*)(g_scr + base) = make_float4(0.f, 0.f, 0.f, 0.f);
    }
}

// ============================================================
// Kernel 2: softmax over 350 logits -> g_w, also writes attn_weights
// (1 block; tiny)
// ============================================================
__global__ __launch_bounds__(128) void k_softmax(float* __restrict__ out)
{
    __shared__ float sw[L];
    __shared__ float red[128];
    int tid = threadIdx.x;

    float m = -INFINITY;
    for (int i = tid; i < L; i += 128) { float v = g_logits[i]; sw[i] = v; m = fmaxf(m, v); }
    red[tid] = m; __syncthreads();
    #pragma unroll
    for (int s = 64; s > 0; s >>= 1) { if (tid < s) red[tid] = fmaxf(red[tid], red[tid+s]); __syncthreads(); }
    float mx = red[0]; __syncthreads();

    float sum = 0.f;
    for (int i = tid; i < L; i += 128) { float e = __expf(sw[i] - mx); sw[i] = e; sum += e; }
    red[tid] = sum; __syncthreads();
    #pragma unroll
    for (int s = 64; s > 0; s >>= 1) { if (tid < s) red[tid] += red[tid+s]; __syncthreads(); }
    float inv = 1.f / red[0]; __syncthreads();

    for (int i = tid; i < L; i += 128) {
        float w = sw[i] * inv;
        g_w[i] = w;
        out[2*H + i] = w;
    }
}

// ============================================================
// Kernel 3: context = g_w @ enc, row-split with atomics.
// grid (16, 7): blockIdx.x -> 128-col chunk, blockIdx.y -> 50-row chunk
// ============================================================
#define CTX_ROWS 50
__global__ __launch_bounds__(128) void k_ctx(const float* __restrict__ enc)
{
    int j  = blockIdx.x * 128 + threadIdx.x;
    int r0 = blockIdx.y * CTX_ROWS;
    const float* e = enc + (size_t)r0 * H + j;
    float acc = 0.f;
    #pragma unroll 10
    for (int i = 0; i < CTX_ROWS; ++i)
        acc += g_w[r0 + i] * e[(size_t)i * H];
    atomicAdd(&g_scr[SC_CTX + j], acc);
}

// ============================================================
// Kernel 4: gsum = comb_W @ [x; ctx]   (K-split: warp per (row, half))
// 4096 warps; dual-stream (x-part + ctx-part interleaved)
// ============================================================
__global__ __launch_bounds__(256) void k_comb(
    const float* __restrict__ x, const float* __restrict__ comb_W)
{
    int gw   = (blockIdx.x * blockDim.x + threadIdx.x) >> 5;
    int lane = threadIdx.x & 31;
    int row  = gw >> 1;
    int half = gw & 1;
    if (row >= H) return;
    const float4* x4 = (const float4*)x;
    const float4* c4 = (const float4*)(g_scr + SC_CTX);
    const float4* W  = (const float4*)(comb_W + (size_t)row * 2 * H);
    int i0 = half * (H4/2);
    float s = 0.f;
    #pragma unroll 4
    for (int i = i0 + lane; i < i0 + H4/2; i += 32) {
        s += dot4(W[i], x4[i]);           // x-part
        s += dot4(W[H4 + i], c4[i]);      // ctx-part
    }
    s = warp_sum(s);
    if (lane == 0) atomicAdd(&g_scr[SC_GSUM + row], s);
}

// ============================================================
// Kernel 5: gi = w_ih @ relu(gsum + comb_b)  (K-split: warp per (col, half))
// 4096 warps; 3 W streams + on-the-fly g computation
// ============================================================
__global__ __launch_bounds__(256) void k_gru_mv(
    const float* __restrict__ w_ih, const float* __restrict__ comb_b)
{
    int gw   = (blockIdx.x * blockDim.x + threadIdx.x) >> 5;
    int lane = threadIdx.x & 31;
    int j    = gw >> 1;
    int half = gw & 1;
    if (j >= H) return;
    const float4* gs = (const float4*)(g_scr + SC_GSUM);
    const float4* cb = (const float4*)comb_b;
    const float4* Wr = (const float4*)(w_ih + (size_t)j * H);
    const float4* Wz = (const float4*)(w_ih + (size_t)(j + H) * H);
    const float4* Wn = (const float4*)(w_ih + (size_t)(j + 2*H) * H);
    int i0 = half * (H4/2);
    float sr = 0.f, sz = 0.f, sn = 0.f;
    #pragma unroll 4
    for (int i = i0 + lane; i < i0 + H4/2; i += 32) {
        float4 gv = gs[i], bv = cb[i];
        float4 v = make_float4(fmaxf(gv.x + bv.x, 0.f), fmaxf(gv.y + bv.y, 0.f),
                               fmaxf(gv.z + bv.z, 0.f), fmaxf(gv.w + bv.w, 0.f));
        sr += dot4(Wr[i], v);
        sz += dot4(Wz[i], v);
        sn += dot4(Wn[i], v);
    }
    sr = warp_sum(sr); sz = warp_sum(sz); sn = warp_sum(sn);
    if (lane == 0) {
        atomicAdd(&g_scr[SC_GI + j],       sr);
        atomicAdd(&g_scr[SC_GI + j + H],   sz);
        atomicAdd(&g_scr[SC_GI + j + 2*H], sn);
    }
}

// ============================================================
// Kernel 6: gate math + outputs (tiny)
// ============================================================
__global__ __launch_bounds__(256) void k_out(
    const float* __restrict__ h, const float* __restrict__ b_ih,
    float* __restrict__ out)
{
    int j = blockIdx.x * blockDim.x + threadIdx.x;
    if (j >= H) return;
    float ir = g_scr[SC_GI + j]       + b_ih[j]       + g_gh[j];
    float iz = g_scr[SC_GI + j + H]   + b_ih[j + H]   + g_gh[j + H];
    float r  = 1.f / (1.f + __expf(-ir));
    float z  = 1.f / (1.f + __expf(-iz));
    float n  = tanhf(g_scr[SC_GI + j + 2*H] + b_ih[j + 2*H] + r * g_gh[j + 2*H]);
    float hn = (1.f - z) * n + z * h[j];
    out[j]     = hn;
    out[H + j] = hn;
}

// ============================================================
extern "C" void kernel_launch(void* const* d_in, const int* in_sizes, int n_in,
                              void* d_out, int out_size)
{
    const float* x      = (const float*)d_in[0];
    const float* h      = (const float*)d_in[1];
    const float* enc    = (const float*)d_in[2];
    const float* attn_W = (const float*)d_in[3];
    const float* attn_b = (const float*)d_in[4];
    const float* comb_W = (const float*)d_in[5];
    const float* comb_b = (const float*)d_in[6];
    const float* w_ih   = (const float*)d_in[7];
    const float* w_hh   = (const float*)d_in[8];
    const float* b_ih   = (const float*)d_in[9];
    const float* b_hh   = (const float*)d_in[10];
    float* out = (float*)d_out;

    k_phase1<<<(P1_WARPS + 7) / 8, 256>>>(x, h, attn_W, attn_b, w_hh, b_hh);
    k_softmax<<<1, 128>>>(out);
    dim3 cgrid(H / 128, L / CTX_ROWS);
    k_ctx<<<cgrid, 128>>>(enc);
    k_comb<<<(2 * H) / 8, 256>>>(x, comb_W);
    k_gru_mv<<<(2 * H) / 8, 256>>>(w_ih, comb_b);
    k_out<<<H / 256, 256>>>(h, b_ih, out);
}

// round 5
// speedup vs baseline: 3.4540x; 1.1989x over previous
#include <cuda_runtime.h>
#include <math.h>

#define H 2048
#define L 350

// -------- persistent scratch (no allocs allowed) --------
__device__ float g_lp[2][L];               // attn logit partials (x-half, h-half)
__device__ float g_w[L];                   // softmax weights
// unified scratch: [0,2048) x copy | [2048,4096) ctx (atomic) |
// [4096,6144) gsum (atomic) | [6144,12288) gi (atomic) | [12288,18432) gh (atomic)
#define SC_VEC   0
#define SC_GSUM  4096
#define SC_GI    6144
#define SC_GH    12288
#define SC_TOTAL 18432
__device__ __align__(16) float g_scr[SC_TOTAL];

__device__ __forceinline__ float warp_sum(float v) {
    #pragma unroll
    for (int o = 16; o > 0; o >>= 1) v += __shfl_xor_sync(0xffffffffu, v, o);
    return v;
}
__device__ __forceinline__ float dot4(float4 a, float4 b) {
    return a.x*b.x + a.y*b.y + a.z*b.z + a.w*b.w;
}

// ============================================================
// kA: attn logit partials (700 warps), zero scratch (128 warps),
//     copy x -> g_scr[SC_VEC] (16 warps).  Small & fast (5.7 MB).
// ============================================================
#define KA_WARPS (700 + 128 + 16)
__global__ __launch_bounds__(256) void kA(
    const float* __restrict__ x, const float* __restrict__ h,
    const float* __restrict__ attn_W)
{
    int warp = (blockIdx.x * blockDim.x + threadIdx.x) >> 5;
    int lane = threadIdx.x & 31;

    if (warp < 700) {
        int row = warp >> 1, half = warp & 1;
        const float4* W = (const float4*)(attn_W + (size_t)row * 2 * H) + half * 512;
        const float4* v = (const float4*)(half ? h : x);
        float s = 0.f;
        #pragma unroll
        for (int i0 = 0; i0 < 512; i0 += 256) {
            float4 w[8];
            #pragma unroll
            for (int u = 0; u < 8; u++) w[u] = __ldcs(&W[i0 + lane + 32*u]);
            #pragma unroll
            for (int u = 0; u < 8; u++) s += dot4(w[u], v[i0 + lane + 32*u]);
        }
        s = warp_sum(s);
        if (lane == 0) g_lp[half][row] = s;
    } else if (warp < 700 + 128) {
        int z = warp - 700;                       // zero [2048, 18432)
        int base = 2048 + z * 128 + lane * 4;
        *(float4*)(g_scr + base) = make_float4(0.f, 0.f, 0.f, 0.f);
    } else if (warp < KA_WARPS) {
        int z = warp - (700 + 128);               // copy x -> [0, 2048)
        int i = z * 32 + lane;
        ((float4*)(g_scr + SC_VEC))[i] = ((const float4*)x)[i];
    }
}

// ============================================================
// kB: softmax over 350 logits (1 block)
// ============================================================
__global__ __launch_bounds__(128) void kB(
    const float* __restrict__ attn_b, float* __restrict__ out)
{
    __shared__ float sw[L];
    __shared__ float red[128];
    int tid = threadIdx.x;

    float m = -INFINITY;
    for (int i = tid; i < L; i += 128) {
        float v = g_lp[0][i] + g_lp[1][i] + attn_b[i];
        sw[i] = v; m = fmaxf(m, v);
    }
    red[tid] = m; __syncthreads();
    #pragma unroll
    for (int s = 64; s > 0; s >>= 1) { if (tid < s) red[tid] = fmaxf(red[tid], red[tid+s]); __syncthreads(); }
    float mx = red[0]; __syncthreads();

    float sum = 0.f;
    for (int i = tid; i < L; i += 128) { float e = __expf(sw[i] - mx); sw[i] = e; sum += e; }
    red[tid] = sum; __syncthreads();
    #pragma unroll
    for (int s = 64; s > 0; s >>= 1) { if (tid < s) red[tid] += red[tid+s]; __syncthreads(); }
    float inv = 1.f / red[0]; __syncthreads();

    for (int i = tid; i < L; i += 128) {
        float w = sw[i] * inv;
        g_w[i] = w;
        out[2*H + i] = w;
    }
}

// ============================================================
// kC: context = g_w @ enc -> g_scr[SC_VEC + 2048 + j]  (row-split, atomic)
// ============================================================
#define CTX_ROWS 50
__global__ __launch_bounds__(128) void kC(const float* __restrict__ enc)
{
    int j  = blockIdx.x * 128 + threadIdx.x;
    int r0 = blockIdx.y * CTX_ROWS;
    const float* e = enc + (size_t)r0 * H + j;
    float acc = 0.f;
    #pragma unroll 10
    for (int i = 0; i < CTX_ROWS; ++i)
        acc += g_w[r0 + i] * e[(size_t)i * H];
    atomicAdd(&g_scr[SC_VEC + 2048 + j], acc);
}

// ============================================================
// kD: comb_W @ vec  (warp per (row, quarter): 8192 warps)
//   + w_hh @ h      (warp per (row, half):   12288 warps)
// 83.6 MB of weight streaming, batched loads.
// ============================================================
#define KD_WARPS (8192 + 12288)
__global__ __launch_bounds__(256) void kD(
    const float* __restrict__ h,
    const float* __restrict__ comb_W, const float* __restrict__ w_hh)
{
    int gw   = (blockIdx.x * blockDim.x + threadIdx.x) >> 5;
    int lane = threadIdx.x & 31;

    if (gw < 8192) {
        int row = gw >> 2, q = gw & 3;
        const float4* W = (const float4*)(comb_W + (size_t)row * 2 * H) + q * 256;
        const float4* v = (const float4*)(g_scr + SC_VEC) + q * 256;
        float4 w[8];
        #pragma unroll
        for (int u = 0; u < 8; u++) w[u] = __ldcs(&W[lane + 32*u]);
        float s = 0.f;
        #pragma unroll
        for (int u = 0; u < 8; u++) s += dot4(w[u], v[lane + 32*u]);
        s = warp_sum(s);
        if (lane == 0) atomicAdd(&g_scr[SC_GSUM + row], s);
    } else {
        int t = gw - 8192;
        int r = t >> 1, half = t & 1;
        const float4* W = (const float4*)(w_hh + (size_t)r * H) + half * 256;
        const float4* v = (const float4*)h + half * 256;
        float4 w[8];
        #pragma unroll
        for (int u = 0; u < 8; u++) w[u] = __ldcs(&W[lane + 32*u]);
        float s = 0.f;
        #pragma unroll
        for (int u = 0; u < 8; u++) s += dot4(w[u], v[lane + 32*u]);
        s = warp_sum(s);
        if (lane == 0) atomicAdd(&g_scr[SC_GH + r], s);
    }
}

// ============================================================
// kE: gi = w_ih @ relu(gsum + comb_b)
// warp per (gate_row, quarter): 24576 warps, single stream
// ============================================================
#define KE_WARPS 24576
__global__ __launch_bounds__(256) void kE(
    const float* __restrict__ w_ih, const float* __restrict__ comb_b)
{
    int gw   = (blockIdx.x * blockDim.x + threadIdx.x) >> 5;
    int lane = threadIdx.x & 31;
    int rr = gw >> 2, q = gw & 3;
    const float4* W  = (const float4*)(w_ih + (size_t)rr * H) + q * 128;
    const float4* gs = (const float4*)(g_scr + SC_GSUM) + q * 128;
    const float4* cb = (const float4*)comb_b + q * 128;
    float4 w[4];
    #pragma unroll
    for (int u = 0; u < 4; u++) w[u] = __ldcs(&W[lane + 32*u]);
    float s = 0.f;
    #pragma unroll
    for (int u = 0; u < 4; u++) {
        float4 gv = gs[lane + 32*u], bv = cb[lane + 32*u];
        float4 v = make_float4(fmaxf(gv.x + bv.x, 0.f), fmaxf(gv.y + bv.y, 0.f),
                               fmaxf(gv.z + bv.z, 0.f), fmaxf(gv.w + bv.w, 0.f));
        s += dot4(w[u], v);
    }
    s = warp_sum(s);
    if (lane == 0) atomicAdd(&g_scr[SC_GI + rr], s);
}

// ============================================================
// kF: GRU gate math + outputs
// ============================================================
__global__ __launch_bounds__(256) void kF(
    const float* __restrict__ h, const float* __restrict__ b_ih,
    const float* __restrict__ b_hh, float* __restrict__ out)
{
    int j = blockIdx.x * blockDim.x + threadIdx.x;
    float hr = g_scr[SC_GH + j]       + b_hh[j];
    float hz = g_scr[SC_GH + j + H]   + b_hh[j + H];
    float hn = g_scr[SC_GH + j + 2*H] + b_hh[j + 2*H];
    float ir = g_scr[SC_GI + j]       + b_ih[j]       + hr;
    float iz = g_scr[SC_GI + j + H]   + b_ih[j + H]   + hz;
    float r  = 1.f / (1.f + __expf(-ir));
    float z  = 1.f / (1.f + __expf(-iz));
    float n  = tanhf(g_scr[SC_GI + j + 2*H] + b_ih[j + 2*H] + r * hn);
    float hv = (1.f - z) * n + z * h[j];
    out[j]     = hv;
    out[H + j] = hv;
}

// ============================================================
extern "C" void kernel_launch(void* const* d_in, const int* in_sizes, int n_in,
                              void* d_out, int out_size)
{
    const float* x      = (const float*)d_in[0];
    const float* h      = (const float*)d_in[1];
    const float* enc    = (const float*)d_in[2];
    const float* attn_W = (const float*)d_in[3];
    const float* attn_b = (const float*)d_in[4];
    const float* comb_W = (const float*)d_in[5];
    const float* comb_b = (const float*)d_in[6];
    const float* w_ih   = (const float*)d_in[7];
    const float* w_hh   = (const float*)d_in[8];
    const float* b_ih   = (const float*)d_in[9];
    const float* b_hh   = (const float*)d_in[10];
    float* out = (float*)d_out;

    kA<<<(KA_WARPS + 7) / 8, 256>>>(x, h, attn_W);
    kB<<<1, 128>>>(attn_b, out);
    dim3 cgrid(H / 128, L / CTX_ROWS);
    kC<<<cgrid, 128>>>(enc);
    kD<<<KD_WARPS / 8, 256>>>(h, comb_W, w_hh);
    kE<<<KE_WARPS / 8, 256>>>(w_ih, comb_b);
    kF<<<H / 256, 256>>>(h, b_ih, b_hh, out);
}

// round 6
// speedup vs baseline: 3.4567x; 1.0008x over previous
#include <cuda_runtime.h>
#include <math.h>

#define H 2048
#define L 350

// -------- persistent scratch (no allocs allowed) --------
__device__ float g_lp[2][L];               // attn logit partials (x-half, h-half)
// unified scratch: [0,2048) x copy | [2048,4096) ctx (atomic, zeroed each replay) |
// [4096,6144) gsum | [6144,12288) gi | [12288,18432) gh
#define SC_VEC   0
#define SC_GSUM  4096
#define SC_GI    6144
#define SC_GH    12288
#define SC_TOTAL 18432
__device__ __align__(16) float g_scr[SC_TOTAL];

__device__ __forceinline__ float warp_sum(float v) {
    #pragma unroll
    for (int o = 16; o > 0; o >>= 1) v += __shfl_xor_sync(0xffffffffu, v, o);
    return v;
}
__device__ __forceinline__ float dot4(float4 a, float4 b) {
    return a.x*b.x + a.y*b.y + a.z*b.z + a.w*b.w;
}

// Pipelined warp-level dot: NB batches of 4 float4 per lane, double-buffered
// weight loads so LDGs stay in flight across the whole row.
template<int NB>
__device__ __forceinline__ float pipelined_dot(
    const float4* __restrict__ W, const float4* __restrict__ V, int lane)
{
    float4 wb[2][4];
    #pragma unroll
    for (int u = 0; u < 4; u++) wb[0][u] = __ldcs(&W[lane + 32*u]);
    float s = 0.f;
    #pragma unroll
    for (int b = 0; b < NB; b++) {
        int cur = b & 1;
        if (b + 1 < NB) {
            #pragma unroll
            for (int u = 0; u < 4; u++)
                wb[cur ^ 1][u] = __ldcs(&W[lane + 32*u + 128*(b+1)]);
        }
        #pragma unroll
        for (int u = 0; u < 4; u++)
            s += dot4(wb[cur][u], V[lane + 32*u + 128*b]);
    }
    return s;
}

// Same, but V = relu(gs + cb) computed on the fly (gs/cb are L1/L2-hot).
template<int NB>
__device__ __forceinline__ float pipelined_dot_relu(
    const float4* __restrict__ W, const float4* __restrict__ gs,
    const float4* __restrict__ cb, int lane)
{
    float4 wb[2][4];
    #pragma unroll
    for (int u = 0; u < 4; u++) wb[0][u] = __ldcs(&W[lane + 32*u]);
    float s = 0.f;
    #pragma unroll
    for (int b = 0; b < NB; b++) {
        int cur = b & 1;
        if (b + 1 < NB) {
            #pragma unroll
            for (int u = 0; u < 4; u++)
                wb[cur ^ 1][u] = __ldcs(&W[lane + 32*u + 128*(b+1)]);
        }
        #pragma unroll
        for (int u = 0; u < 4; u++) {
            int i = lane + 32*u + 128*b;
            float4 gv = gs[i], bv = cb[i];
            float4 v = make_float4(fmaxf(gv.x + bv.x, 0.f), fmaxf(gv.y + bv.y, 0.f),
                                   fmaxf(gv.z + bv.z, 0.f), fmaxf(gv.w + bv.w, 0.f));
            s += dot4(wb[cur][u], v);
        }
    }
    return s;
}

// ============================================================
// kA: attn logit partials (700 warps, pipelined) + zero ctx (16 warps)
//     + copy x -> g_scr[SC_VEC] (16 warps)
// ============================================================
#define KA_WARPS (700 + 16 + 16)
__global__ __launch_bounds__(256) void kA(
    const float* __restrict__ x, const float* __restrict__ h,
    const float* __restrict__ attn_W)
{
    int warp = (blockIdx.x * blockDim.x + threadIdx.x) >> 5;
    int lane = threadIdx.x & 31;

    if (warp < 700) {
        int row = warp >> 1, half = warp & 1;
        const float4* W = (const float4*)(attn_W + (size_t)row * 2 * H) + half * 512;
        const float4* v = (const float4*)(half ? h : x);
        float s = pipelined_dot<4>(W, v, lane);
        s = warp_sum(s);
        if (lane == 0) g_lp[half][row] = s;
    } else if (warp < 716) {
        int z = warp - 700;                   // zero ctx region [2048,4096)
        *(float4*)(g_scr + 2048 + z * 128 + lane * 4) = make_float4(0.f,0.f,0.f,0.f);
    } else if (warp < KA_WARPS) {
        int z = warp - 716;                   // copy x -> [0,2048)
        int i = z * 32 + lane;
        ((float4*)(g_scr + SC_VEC))[i] = ((const float4*)x)[i];
    }
}

// ============================================================
// kBC: per-block redundant softmax over 350 logits (L2-hit) + ctx partial.
// grid (16, 7): bx -> 128-col chunk, by -> 50-row chunk.
// Block (0,0) also writes attn_weights to out.
// ============================================================
#define CTX_ROWS 50
__global__ __launch_bounds__(128) void kBC(
    const float* __restrict__ attn_b, const float* __restrict__ enc,
    float* __restrict__ out)
{
    __shared__ float sw[L];
    __shared__ float red[128];
    int tid = threadIdx.x;

    float m = -INFINITY;
    for (int i = tid; i < L; i += 128) {
        float v = g_lp[0][i] + g_lp[1][i] + attn_b[i];
        sw[i] = v; m = fmaxf(m, v);
    }
    red[tid] = m; __syncthreads();
    #pragma unroll
    for (int s = 64; s > 0; s >>= 1) { if (tid < s) red[tid] = fmaxf(red[tid], red[tid+s]); __syncthreads(); }
    float mx = red[0]; __syncthreads();

    float sum = 0.f;
    for (int i = tid; i < L; i += 128) { float e = __expf(sw[i] - mx); sw[i] = e; sum += e; }
    red[tid] = sum; __syncthreads();
    #pragma unroll
    for (int s = 64; s > 0; s >>= 1) { if (tid < s) red[tid] += red[tid+s]; __syncthreads(); }
    float inv = 1.f / red[0]; __syncthreads();
    for (int i = tid; i < L; i += 128) sw[i] *= inv;
    __syncthreads();

    if (blockIdx.x == 0 && blockIdx.y == 0)
        for (int i = tid; i < L; i += 128) out[2*H + i] = sw[i];

    int j  = blockIdx.x * 128 + tid;
    int r0 = blockIdx.y * CTX_ROWS;
    const float* e = enc + (size_t)r0 * H + j;
    float acc = 0.f;
    #pragma unroll 10
    for (int i = 0; i < CTX_ROWS; ++i)
        acc += sw[r0 + i] * e[(size_t)i * H];
    atomicAdd(&g_scr[SC_VEC + 2048 + j], acc);
}

// ============================================================
// kD: comb_W @ vec (2048 warps, 8 batches) + w_hh @ h (6144 warps, 4 batches)
// warp-per-row, pipelined, direct stores (no atomics).
// ============================================================
#define KD_WARPS (2048 + 6144)
__global__ __launch_bounds__(256) void kD(
    const float* __restrict__ h,
    const float* __restrict__ comb_W, const float* __restrict__ w_hh)
{
    int gw   = (blockIdx.x * blockDim.x + threadIdx.x) >> 5;
    int lane = threadIdx.x & 31;

    if (gw < 2048) {
        int row = gw;
        const float4* W = (const float4*)(comb_W + (size_t)row * 2 * H);
        const float4* v = (const float4*)(g_scr + SC_VEC);
        float s = pipelined_dot<8>(W, v, lane);
        s = warp_sum(s);
        if (lane == 0) g_scr[SC_GSUM + row] = s;
    } else {
        int r = gw - 2048;
        const float4* W = (const float4*)(w_hh + (size_t)r * H);
        const float4* v = (const float4*)h;
        float s = pipelined_dot<4>(W, v, lane);
        s = warp_sum(s);
        if (lane == 0) g_scr[SC_GH + r] = s;
    }
}

// ============================================================
// kE: gi = w_ih @ relu(gsum + comb_b)  (6144 warps, 4 batches, pipelined)
// ============================================================
#define KE_WARPS 6144
__global__ __launch_bounds__(256) void kE(
    const float* __restrict__ w_ih, const float* __restrict__ comb_b)
{
    int gw   = (blockIdx.x * blockDim.x + threadIdx.x) >> 5;
    int lane = threadIdx.x & 31;
    const float4* W  = (const float4*)(w_ih + (size_t)gw * H);
    const float4* gs = (const float4*)(g_scr + SC_GSUM);
    const float4* cb = (const float4*)comb_b;
    float s = pipelined_dot_relu<4>(W, gs, cb, lane);
    s = warp_sum(s);
    if (lane == 0) g_scr[SC_GI + gw] = s;
}

// ============================================================
// kF: GRU gate math + outputs
// ============================================================
__global__ __launch_bounds__(256) void kF(
    const float* __restrict__ h, const float* __restrict__ b_ih,
    const float* __restrict__ b_hh, float* __restrict__ out)
{
    int j = blockIdx.x * blockDim.x + threadIdx.x;
    float hr = g_scr[SC_GH + j]       + b_hh[j];
    float hz = g_scr[SC_GH + j + H]   + b_hh[j + H];
    float hn = g_scr[SC_GH + j + 2*H] + b_hh[j + 2*H];
    float ir = g_scr[SC_GI + j]       + b_ih[j]       + hr;
    float iz = g_scr[SC_GI + j + H]   + b_ih[j + H]   + hz;
    float r  = 1.f / (1.f + __expf(-ir));
    float z  = 1.f / (1.f + __expf(-iz));
    float n  = tanhf(g_scr[SC_GI + j + 2*H] + b_ih[j + 2*H] + r * hn);
    float hv = (1.f - z) * n + z * h[j];
    out[j]     = hv;
    out[H + j] = hv;
}

// ============================================================
extern "C" void kernel_launch(void* const* d_in, const int* in_sizes, int n_in,
                              void* d_out, int out_size)
{
    const float* x      = (const float*)d_in[0];
    const float* h      = (const float*)d_in[1];
    const float* enc    = (const float*)d_in[2];
    const float* attn_W = (const float*)d_in[3];
    const float* attn_b = (const float*)d_in[4];
    const float* comb_W = (const float*)d_in[5];
    const float* comb_b = (const float*)d_in[6];
    const float* w_ih   = (const float*)d_in[7];
    const float* w_hh   = (const float*)d_in[8];
    const float* b_ih   = (const float*)d_in[9];
    const float* b_hh   = (const float*)d_in[10];
    float* out = (float*)d_out;

    kA<<<(KA_WARPS + 7) / 8, 256>>>(x, h, attn_W);
    dim3 cgrid(H / 128, L / CTX_ROWS);
    kBC<<<cgrid, 128>>>(attn_b, enc, out);
    kD<<<KD_WARPS / 8, 256>>>(h, comb_W, w_hh);
    kE<<<KE_WARPS / 8, 256>>>(w_ih, comb_b);
    kF<<<H / 256, 256>>>(h, b_ih, b_hh, out);
}

// round 7
// speedup vs baseline: 3.6385x; 1.0526x over previous
#include <cuda_runtime.h>
#include <math.h>

#define H 2048
#define L 350

// -------- persistent scratch (no allocs allowed) --------
__device__ float g_lp[2][L];               // attn logit partials (x-half, h-half)
// unified scratch: [0,2048) x copy | [2048,4096) ctx (atomic, zeroed each replay) |
// [4096,6144) gsum | [6144,12288) gi | [12288,18432) gh
#define SC_VEC   0
#define SC_GSUM  4096
#define SC_GI    6144
#define SC_GH    12288
#define SC_TOTAL 18432
__device__ __align__(16) float g_scr[SC_TOTAL];

__device__ __forceinline__ float warp_sum(float v) {
    #pragma unroll
    for (int o = 16; o > 0; o >>= 1) v += __shfl_xor_sync(0xffffffffu, v, o);
    return v;
}
__device__ __forceinline__ float dot4(float4 a, float4 b) {
    return a.x*b.x + a.y*b.y + a.z*b.z + a.w*b.w;
}

// Pipelined warp dot with the vector in SHARED memory: weight LDGs are the
// only global traffic; double-buffered so the stream never drains.
template<int NB>
__device__ __forceinline__ float pipelined_dot_sv(
    const float4* __restrict__ W, const float4* sv, int lane)
{
    float4 wb[2][4];
    #pragma unroll
    for (int u = 0; u < 4; u++) wb[0][u] = __ldcs(&W[lane + 32*u]);
    float s = 0.f;
    #pragma unroll
    for (int b = 0; b < NB; b++) {
        int cur = b & 1;
        if (b + 1 < NB) {
            #pragma unroll
            for (int u = 0; u < 4; u++)
                wb[cur ^ 1][u] = __ldcs(&W[lane + 32*u + 128*(b+1)]);
        }
        #pragma unroll
        for (int u = 0; u < 4; u++)
            s += dot4(wb[cur][u], sv[lane + 32*u + 128*b]);
    }
    return s;
}

// Global-vector variant (used only in small kA).
template<int NB>
__device__ __forceinline__ float pipelined_dot(
    const float4* __restrict__ W, const float4* __restrict__ V, int lane)
{
    float4 wb[2][4];
    #pragma unroll
    for (int u = 0; u < 4; u++) wb[0][u] = __ldcs(&W[lane + 32*u]);
    float s = 0.f;
    #pragma unroll
    for (int b = 0; b < NB; b++) {
        int cur = b & 1;
        if (b + 1 < NB) {
            #pragma unroll
            for (int u = 0; u < 4; u++)
                wb[cur ^ 1][u] = __ldcs(&W[lane + 32*u + 128*(b+1)]);
        }
        #pragma unroll
        for (int u = 0; u < 4; u++)
            s += dot4(wb[cur][u], V[lane + 32*u + 128*b]);
    }
    return s;
}

// ============================================================
// kA: attn logit partials (700 warps) + zero ctx (16) + copy x (16)
// ============================================================
#define KA_WARPS (700 + 16 + 16)
__global__ __launch_bounds__(256) void kA(
    const float* __restrict__ x, const float* __restrict__ h,
    const float* __restrict__ attn_W)
{
    int warp = (blockIdx.x * blockDim.x + threadIdx.x) >> 5;
    int lane = threadIdx.x & 31;

    if (warp < 700) {
        int row = warp >> 1, half = warp & 1;
        const float4* W = (const float4*)(attn_W + (size_t)row * 2 * H) + half * 512;
        const float4* v = (const float4*)(half ? h : x);
        float s = pipelined_dot<4>(W, v, lane);
        s = warp_sum(s);
        if (lane == 0) g_lp[half][row] = s;
    } else if (warp < 716) {
        int z = warp - 700;                   // zero ctx region [2048,4096)
        *(float4*)(g_scr + 2048 + z * 128 + lane * 4) = make_float4(0.f,0.f,0.f,0.f);
    } else if (warp < KA_WARPS) {
        int z = warp - 716;                   // copy x -> [0,2048)
        int i = z * 32 + lane;
        ((float4*)(g_scr + SC_VEC))[i] = ((const float4*)x)[i];
    }
}

// ============================================================
// kBC: per-block redundant softmax (L2-hot) + ctx partial.
// grid (16, 14): bx -> 128-col chunk, by -> 25-row chunk.
// ============================================================
#define CTX_ROWS 25
__global__ __launch_bounds__(128) void kBC(
    const float* __restrict__ attn_b, const float* __restrict__ enc,
    float* __restrict__ out)
{
    __shared__ float sw[L];
    __shared__ float red[128];
    int tid = threadIdx.x;

    float m = -INFINITY;
    for (int i = tid; i < L; i += 128) {
        float v = g_lp[0][i] + g_lp[1][i] + attn_b[i];
        sw[i] = v; m = fmaxf(m, v);
    }
    red[tid] = m; __syncthreads();
    #pragma unroll
    for (int s = 64; s > 0; s >>= 1) { if (tid < s) red[tid] = fmaxf(red[tid], red[tid+s]); __syncthreads(); }
    float mx = red[0]; __syncthreads();

    float sum = 0.f;
    for (int i = tid; i < L; i += 128) { float e = __expf(sw[i] - mx); sw[i] = e; sum += e; }
    red[tid] = sum; __syncthreads();
    #pragma unroll
    for (int s = 64; s > 0; s >>= 1) { if (tid < s) red[tid] += red[tid+s]; __syncthreads(); }
    float inv = 1.f / red[0]; __syncthreads();
    for (int i = tid; i < L; i += 128) sw[i] *= inv;
    __syncthreads();

    if (blockIdx.x == 0 && blockIdx.y == 0)
        for (int i = tid; i < L; i += 128) out[2*H + i] = sw[i];

    int j  = blockIdx.x * 128 + tid;
    int r0 = blockIdx.y * CTX_ROWS;
    const float* e = enc + (size_t)r0 * H + j;
    float acc = 0.f;
    #pragma unroll
    for (int i = 0; i < CTX_ROWS; ++i)
        acc += sw[r0 + i] * e[(size_t)i * H];
    atomicAdd(&g_scr[SC_VEC + 2048 + j], acc);
}

// ============================================================
// kD: blocks 0..255  -> comb_W @ vec (smem-staged 16 KB vector, 8 batches)
//     blocks 256..1023 -> w_hh @ h  (smem-staged 8 KB vector, 4 batches)
// warp-per-row, direct stores.
// ============================================================
#define KD_BLOCKS (256 + 768)
__global__ __launch_bounds__(256) void kD(
    const float* __restrict__ h,
    const float* __restrict__ comb_W, const float* __restrict__ w_hh)
{
    __shared__ __align__(16) float sv[4096];
    float4* sv4 = (float4*)sv;
    int tid  = threadIdx.x;
    int lane = tid & 31;
    int wid  = tid >> 5;

    if (blockIdx.x < 256) {
        // stage [x;ctx] (1024 float4)
        const float4* gv = (const float4*)(g_scr + SC_VEC);
        #pragma unroll
        for (int i = tid; i < 1024; i += 256) sv4[i] = gv[i];
        __syncthreads();
        int row = blockIdx.x * 8 + wid;
        const float4* W = (const float4*)(comb_W + (size_t)row * 2 * H);
        float s = pipelined_dot_sv<8>(W, sv4, lane);
        s = warp_sum(s);
        if (lane == 0) g_scr[SC_GSUM + row] = s;
    } else {
        // stage h (512 float4)
        const float4* gv = (const float4*)h;
        #pragma unroll
        for (int i = tid; i < 512; i += 256) sv4[i] = gv[i];
        __syncthreads();
        int r = (blockIdx.x - 256) * 8 + wid;
        const float4* W = (const float4*)(w_hh + (size_t)r * H);
        float s = pipelined_dot_sv<4>(W, sv4, lane);
        s = warp_sum(s);
        if (lane == 0) g_scr[SC_GH + r] = s;
    }
}

// ============================================================
// kE: gi = w_ih @ relu(gsum + comb_b); relu vector staged in smem.
// 768 blocks, warp-per-row.
// ============================================================
#define KE_BLOCKS 768
__global__ __launch_bounds__(256) void kE(
    const float* __restrict__ w_ih, const float* __restrict__ comb_b)
{
    __shared__ __align__(16) float sv[2048];
    float4* sv4 = (float4*)sv;
    int tid  = threadIdx.x;
    int lane = tid & 31;
    int wid  = tid >> 5;

    const float4* gs = (const float4*)(g_scr + SC_GSUM);
    const float4* cb = (const float4*)comb_b;
    #pragma unroll
    for (int i = tid; i < 512; i += 256) {
        float4 gv = gs[i], bv = cb[i];
        sv4[i] = make_float4(fmaxf(gv.x + bv.x, 0.f), fmaxf(gv.y + bv.y, 0.f),
                             fmaxf(gv.z + bv.z, 0.f), fmaxf(gv.w + bv.w, 0.f));
    }
    __syncthreads();

    int row = blockIdx.x * 8 + wid;
    const float4* W = (const float4*)(w_ih + (size_t)row * H);
    float s = pipelined_dot_sv<4>(W, sv4, lane);
    s = warp_sum(s);
    if (lane == 0) g_scr[SC_GI + row] = s;
}

// ============================================================
// kF: GRU gate math + outputs
// ============================================================
__global__ __launch_bounds__(256) void kF(
    const float* __restrict__ h, const float* __restrict__ b_ih,
    const float* __restrict__ b_hh, float* __restrict__ out)
{
    int j = blockIdx.x * blockDim.x + threadIdx.x;
    float hr = g_scr[SC_GH + j]       + b_hh[j];
    float hz = g_scr[SC_GH + j + H]   + b_hh[j + H];
    float hn = g_scr[SC_GH + j + 2*H] + b_hh[j + 2*H];
    float ir = g_scr[SC_GI + j]       + b_ih[j]       + hr;
    float iz = g_scr[SC_GI + j + H]   + b_ih[j + H]   + hz;
    float r  = 1.f / (1.f + __expf(-ir));
    float z  = 1.f / (1.f + __expf(-iz));
    float n  = tanhf(g_scr[SC_GI + j + 2*H] + b_ih[j + 2*H] + r * hn);
    float hv = (1.f - z) * n + z * h[j];
    out[j]     = hv;
    out[H + j] = hv;
}

// ============================================================
extern "C" void kernel_launch(void* const* d_in, const int* in_sizes, int n_in,
                              void* d_out, int out_size)
{
    const float* x      = (const float*)d_in[0];
    const float* h      = (const float*)d_in[1];
    const float* enc    = (const float*)d_in[2];
    const float* attn_W = (const float*)d_in[3];
    const float* attn_b = (const float*)d_in[4];
    const float* comb_W = (const float*)d_in[5];
    const float* comb_b = (const float*)d_in[6];
    const float* w_ih   = (const float*)d_in[7];
    const float* w_hh   = (const float*)d_in[8];
    const float* b_ih   = (const float*)d_in[9];
    const float* b_hh   = (const float*)d_in[10];
    float* out = (float*)d_out;

    kA<<<(KA_WARPS + 7) / 8, 256>>>(x, h, attn_W);
    dim3 cgrid(H / 128, L / CTX_ROWS);
    kBC<<<cgrid, 128>>>(attn_b, enc, out);
    kD<<<KD_BLOCKS, 256>>>(h, comb_W, w_hh);
    kE<<<KE_BLOCKS, 256>>>(w_ih, comb_b);
    kF<<<H / 256, 256>>>(h, b_ih, b_hh, out);
}